// round 7
// baseline (speedup 1.0000x reference)
#include <cuda_runtime.h>
#include <cstdint>

#define NHEAD 16
#define QLEN  4096
#define KLEN  4096
#define DIM   64
#define BQ    128
#define BK    64
#define NTHREADS 128
#define NITER (KLEN / BK)

#define KSS 68   // K tile stride (floats): B-frag loads conflict-free
#define VSS 72   // V tile stride: conflict-free
#define PSS 68   // P pad stride: A-frag loads conflict-free

#define STAGE_K_FLOATS (64 * KSS)                      // 4352
#define STAGE_FLOATS   (STAGE_K_FLOATS + 64 * VSS)     // 8960
#define PS_OFF         (2 * STAGE_FLOATS)              // 17920
#define SMEM_FLOATS    (PS_OFF + 4 * 32 * PSS)         // 26624
#define SMEM_BYTES     (SMEM_FLOATS * 4)               // 106496

// pre-rounded tf32 K/V scratch (static __device__: allocation-free)
__device__ uint32_t g_Kr[NHEAD * KLEN * DIM];
__device__ uint32_t g_Vr[NHEAD * KLEN * DIM];

__device__ __forceinline__ uint32_t f2tf(float x) {
    uint32_t r; asm("cvt.rna.tf32.f32 %0, %1;" : "=r"(r) : "f"(x)); return r;
}
__device__ __forceinline__ float fast_exp2(float x) {
    float y; asm("ex2.approx.ftz.f32 %0, %1;" : "=f"(y) : "f"(x)); return y;
}
__device__ __forceinline__ uint32_t smem_u32(const void* p) {
    uint32_t a;
    asm("{ .reg .u64 t; cvta.to.shared.u64 t, %1; cvt.u32.u64 %0, t; }" : "=r"(a) : "l"(p));
    return a;
}
__device__ __forceinline__ void cp16(uint32_t dst, const void* src) {
    asm volatile("cp.async.ca.shared.global [%0], [%1], 16;" :: "r"(dst), "l"(src) : "memory");
}
#define CP_COMMIT() asm volatile("cp.async.commit_group;" ::: "memory")
#define CP_WAIT1()  asm volatile("cp.async.wait_group 1;" ::: "memory")

// D(16x8,f32) += A(16x8,tf32) * B(8x8,tf32)   [row.col]
__device__ __forceinline__ void mma_tf32(float* d, const uint32_t* a,
                                         uint32_t b0, uint32_t b1) {
    asm volatile(
        "mma.sync.aligned.m16n8k8.row.col.f32.tf32.tf32.f32 "
        "{%0,%1,%2,%3}, {%4,%5,%6,%7}, {%8,%9}, {%0,%1,%2,%3};"
        : "+f"(d[0]), "+f"(d[1]), "+f"(d[2]), "+f"(d[3])
        : "r"(a[0]), "r"(a[1]), "r"(a[2]), "r"(a[3]), "r"(b0), "r"(b1));
}

// ---- prepass: round K,V to tf32 (rna) once ----
extern "C" __global__ void __launch_bounds__(256)
kv_round(const float* __restrict__ ks, const float* __restrict__ vs)
{
    const size_t i = (size_t)blockIdx.x * blockDim.x + threadIdx.x;  // float4 index
    float4 k = ((const float4*)ks)[i];
    ((uint4*)g_Kr)[i] = make_uint4(f2tf(k.x), f2tf(k.y), f2tf(k.z), f2tf(k.w));
    float4 v = ((const float4*)vs)[i];
    ((uint4*)g_Vr)[i] = make_uint4(f2tf(v.x), f2tf(v.y), f2tf(v.z), f2tf(v.w));
}

// online-softmax update for one 32-key half (j = jbase..jbase+3)
__device__ __forceinline__ void softmax_half(
    float sacc[8][8], int jbase, const unsigned int* __restrict__ maskw,
    int kb, int b, float mrun[4], float lrun[4], float al[4])
{
    // mask (robust word-of-4; all-true -> never taken)
    #pragma unroll
    for (int jj = 0; jj < 4; jj++) {
        const int j = jbase + jj;
        if (maskw[kb + 2 * j + (b >> 1)] == 0u) {
            #pragma unroll
            for (int e = 0; e < 8; e++) sacc[j][e] = -1e30f;
        }
    }
    float m[4] = {-1e30f, -1e30f, -1e30f, -1e30f};
    #pragma unroll
    for (int jj = 0; jj < 4; jj++) {
        const int j = jbase + jj;
        #pragma unroll
        for (int i = 0; i < 4; i++)
            m[i] = fmaxf(m[i], fmaxf(sacc[j][2 * i], sacc[j][2 * i + 1]));
    }
    #pragma unroll
    for (int i = 0; i < 4; i++) {
        m[i] = fmaxf(m[i], __shfl_xor_sync(0xffffffffu, m[i], 1));
        m[i] = fmaxf(m[i], __shfl_xor_sync(0xffffffffu, m[i], 2));
    }
    #pragma unroll
    for (int i = 0; i < 4; i++) {
        const float mn = fmaxf(mrun[i], m[i]);
        al[i] = fast_exp2(mrun[i] - mn);
        mrun[i] = mn;
    }
    float l[4] = {0.0f, 0.0f, 0.0f, 0.0f};
    #pragma unroll
    for (int jj = 0; jj < 4; jj++) {
        const int j = jbase + jj;
        #pragma unroll
        for (int i = 0; i < 4; i++) {
            sacc[j][2 * i]     = fast_exp2(sacc[j][2 * i]     - mrun[i]);
            sacc[j][2 * i + 1] = fast_exp2(sacc[j][2 * i + 1] - mrun[i]);
            l[i] += sacc[j][2 * i] + sacc[j][2 * i + 1];
        }
    }
    #pragma unroll
    for (int i = 0; i < 4; i++) {
        l[i] += __shfl_xor_sync(0xffffffffu, l[i], 1);
        l[i] += __shfl_xor_sync(0xffffffffu, l[i], 2);
        lrun[i] = lrun[i] * al[i] + l[i];
    }
}

extern "C" __global__ void __launch_bounds__(NTHREADS, 2)
fa_hmma_ovl(const float* __restrict__ qs, const unsigned int* __restrict__ maskw,
            float* __restrict__ out)
{
    extern __shared__ float sm[];
    const uint32_t sb = smem_u32(sm);

    const int tid  = threadIdx.x;
    const int w    = tid >> 5;
    const int lane = tid & 31;
    const int g    = lane >> 2;   // row within 8
    const int b    = lane & 3;    // k/col selector

    uint32_t* PwU = (uint32_t*)(sm + PS_OFF) + w * 32 * PSS;  // warp P pad [32][PSS]

    const int head = blockIdx.y;
    const int q0   = blockIdx.x * BQ;
    const int r0   = w * 32 + g;             // rows r0, +8, +16, +24

    const float qscale = 0.125f * 1.44269504088896340736f;  // 1/sqrt(D) * log2(e)
    const float* qg = qs + ((size_t)head * QLEN + q0) * DIM;
    const uint32_t* kg = g_Kr + (size_t)head * KLEN * DIM;
    const uint32_t* vg = g_Vr + (size_t)head * KLEN * DIM;

    const int srow = tid >> 4;              // cp.async row base
    const int scol = (tid & 15) * 4;        // cp.async col (floats)

    // ---- prologue: prefetch stage 0 ----
    {
        #pragma unroll
        for (int i = 0; i < 8; i++) {
            const int r = srow + 8 * i;
            cp16(sb + (r * KSS + scol) * 4, kg + (size_t)r * DIM + scol);
            cp16(sb + (STAGE_K_FLOATS + r * VSS + scol) * 4, vg + (size_t)r * DIM + scol);
        }
        CP_COMMIT();
    }

    // ---- persistent Q A-fragments ----
    uint32_t qa[8][8];
    {
        const float* q0p = qg + (size_t)r0 * DIM;
        const float* q1p = q0p + 8 * DIM;
        const float* q2p = q0p + 16 * DIM;
        const float* q3p = q0p + 24 * DIM;
        #pragma unroll
        for (int c = 0; c < 8; c++) {
            const int k0c = c * 8 + b;
            qa[c][0] = f2tf(q0p[k0c]     * qscale);
            qa[c][1] = f2tf(q1p[k0c]     * qscale);
            qa[c][2] = f2tf(q0p[k0c + 4] * qscale);
            qa[c][3] = f2tf(q1p[k0c + 4] * qscale);
            qa[c][4] = f2tf(q2p[k0c]     * qscale);
            qa[c][5] = f2tf(q3p[k0c]     * qscale);
            qa[c][6] = f2tf(q2p[k0c + 4] * qscale);
            qa[c][7] = f2tf(q3p[k0c + 4] * qscale);
        }
    }

    float o[8][8];
    #pragma unroll
    for (int j = 0; j < 8; j++)
        #pragma unroll
        for (int e = 0; e < 8; e++) o[j][e] = 0.0f;
    float mrun[4] = {-1e30f, -1e30f, -1e30f, -1e30f};
    float lrun[4] = {0.0f, 0.0f, 0.0f, 0.0f};

    for (int it = 0; it < NITER; it++) {
        const int k0 = it * BK;
        const int stage = it & 1;
        const int kb = k0 >> 2;

        // ---- prefetch next tile into other stage ----
        {
            const int knx = (it + 1 < NITER ? it + 1 : it) * BK;
            const uint32_t sbase = sb + ((1 - stage) * STAGE_FLOATS) * 4;
            #pragma unroll
            for (int i = 0; i < 8; i++) {
                const int r = srow + 8 * i;
                cp16(sbase + (r * KSS + scol) * 4, kg + (size_t)(knx + r) * DIM + scol);
                cp16(sbase + (STAGE_K_FLOATS + r * VSS + scol) * 4,
                     vg + (size_t)(knx + r) * DIM + scol);
            }
            CP_COMMIT();
        }
        CP_WAIT1();
        __syncthreads();

        const uint32_t* KsU = (const uint32_t*)(sm + stage * STAGE_FLOATS);
        const uint32_t* VsU = KsU + STAGE_K_FLOATS;

        float sacc[8][8];
        #pragma unroll
        for (int j = 0; j < 8; j++)
            #pragma unroll
            for (int e = 0; e < 8; e++) sacc[j][e] = 0.0f;

        // ---- MMA1 half0 (keys 0..31 of block: j=0..3) ----
        #pragma unroll
        for (int c = 0; c < 8; c++) {
            #pragma unroll
            for (int j = 0; j < 4; j++) {
                const uint32_t* kp = &KsU[(j * 8 + g) * KSS + c * 8 + b];
                const uint32_t kb0 = kp[0], kb1 = kp[4];
                mma_tf32(&sacc[j][0], &qa[c][0], kb0, kb1);
                mma_tf32(&sacc[j][4], &qa[c][4], kb0, kb1);
            }
        }
        // ---- MMA1 half1 issued now: its HMMAs overlap half0's softmax ----
        #pragma unroll
        for (int c = 0; c < 8; c++) {
            #pragma unroll
            for (int j = 4; j < 8; j++) {
                const uint32_t* kp = &KsU[(j * 8 + g) * KSS + c * 8 + b];
                const uint32_t kb0 = kp[0], kb1 = kp[4];
                mma_tf32(&sacc[j][0], &qa[c][0], kb0, kb1);
                mma_tf32(&sacc[j][4], &qa[c][4], kb0, kb1);
            }
        }

        // ---- softmax half0 (MUFU overlaps half1 HMMAs) ----
        float al[4];
        softmax_half(sacc, 0, maskw, kb, b, mrun, lrun, al);

        #pragma unroll
        for (int j = 0; j < 4; j++) {
            const int col = j * 8 + 2 * b;
            *(uint2*)&PwU[ g       * PSS + col] = make_uint2(f2tf(sacc[j][0]), f2tf(sacc[j][1]));
            *(uint2*)&PwU[(g +  8) * PSS + col] = make_uint2(f2tf(sacc[j][2]), f2tf(sacc[j][3]));
            *(uint2*)&PwU[(g + 16) * PSS + col] = make_uint2(f2tf(sacc[j][4]), f2tf(sacc[j][5]));
            *(uint2*)&PwU[(g + 24) * PSS + col] = make_uint2(f2tf(sacc[j][6]), f2tf(sacc[j][7]));
        }
        #pragma unroll
        for (int j = 0; j < 8; j++) {
            #pragma unroll
            for (int i = 0; i < 4; i++) {
                o[j][2 * i]     *= al[i];
                o[j][2 * i + 1] *= al[i];
            }
        }
        __syncwarp();

        // ---- PV half0 (kc 0..3) ----
        #pragma unroll
        for (int kc = 0; kc < 4; kc++) {
            uint32_t pa0[4], pa1[4];
            const int kcol = kc * 8 + b;
            pa0[0] = PwU[ g       * PSS + kcol];
            pa0[1] = PwU[(g +  8) * PSS + kcol];
            pa0[2] = PwU[ g       * PSS + kcol + 4];
            pa0[3] = PwU[(g +  8) * PSS + kcol + 4];
            pa1[0] = PwU[(g + 16) * PSS + kcol];
            pa1[1] = PwU[(g + 24) * PSS + kcol];
            pa1[2] = PwU[(g + 16) * PSS + kcol + 4];
            pa1[3] = PwU[(g + 24) * PSS + kcol + 4];
            #pragma unroll
            for (int j = 0; j < 8; j++) {
                const uint32_t v0 = VsU[(kc * 8 + b)     * VSS + j * 8 + g];
                const uint32_t v1 = VsU[(kc * 8 + b + 4) * VSS + j * 8 + g];
                mma_tf32(&o[j][0], pa0, v0, v1);
                mma_tf32(&o[j][4], pa1, v0, v1);
            }
        }

        // ---- softmax half1 (MUFU overlaps PV-half0 HMMAs) ----
        float al2[4];
        softmax_half(sacc, 4, maskw, kb, b, mrun, lrun, al2);

        #pragma unroll
        for (int j = 4; j < 8; j++) {
            const int col = j * 8 + 2 * b;
            *(uint2*)&PwU[ g       * PSS + col] = make_uint2(f2tf(sacc[j][0]), f2tf(sacc[j][1]));
            *(uint2*)&PwU[(g +  8) * PSS + col] = make_uint2(f2tf(sacc[j][2]), f2tf(sacc[j][3]));
            *(uint2*)&PwU[(g + 16) * PSS + col] = make_uint2(f2tf(sacc[j][4]), f2tf(sacc[j][5]));
            *(uint2*)&PwU[(g + 24) * PSS + col] = make_uint2(f2tf(sacc[j][6]), f2tf(sacc[j][7]));
        }
        // o-rescale by al2 waits (scoreboard) for PV-half0 to retire
        #pragma unroll
        for (int j = 0; j < 8; j++) {
            #pragma unroll
            for (int i = 0; i < 4; i++) {
                o[j][2 * i]     *= al2[i];
                o[j][2 * i + 1] *= al2[i];
            }
        }
        __syncwarp();

        // ---- PV half1 (kc 4..7) ----
        #pragma unroll
        for (int kc = 4; kc < 8; kc++) {
            uint32_t pa0[4], pa1[4];
            const int kcol = kc * 8 + b;
            pa0[0] = PwU[ g       * PSS + kcol];
            pa0[1] = PwU[(g +  8) * PSS + kcol];
            pa0[2] = PwU[ g       * PSS + kcol + 4];
            pa0[3] = PwU[(g +  8) * PSS + kcol + 4];
            pa1[0] = PwU[(g + 16) * PSS + kcol];
            pa1[1] = PwU[(g + 24) * PSS + kcol];
            pa1[2] = PwU[(g + 16) * PSS + kcol + 4];
            pa1[3] = PwU[(g + 24) * PSS + kcol + 4];
            #pragma unroll
            for (int j = 0; j < 8; j++) {
                const uint32_t v0 = VsU[(kc * 8 + b)     * VSS + j * 8 + g];
                const uint32_t v1 = VsU[(kc * 8 + b + 4) * VSS + j * 8 + g];
                mma_tf32(&o[j][0], pa0, v0, v1);
                mma_tf32(&o[j][4], pa1, v0, v1);
            }
        }
        __syncwarp();

        __syncthreads();  // all reads of this stage done before re-fill
    }

    // ---- epilogue: normalize + store ----
    {
        float inv[4];
        #pragma unroll
        for (int i = 0; i < 4; i++) inv[i] = (lrun[i] > 0.0f) ? (1.0f / lrun[i]) : 0.0f;
        float* orow = out + ((size_t)head * QLEN + q0 + r0) * DIM;
        #pragma unroll
        for (int j = 0; j < 8; j++) {
            const int col = j * 8 + 2 * b;
            *(float2*)&orow[ 0 * DIM + col] = make_float2(o[j][0] * inv[0], o[j][1] * inv[0]);
            *(float2*)&orow[ 8 * DIM + col] = make_float2(o[j][2] * inv[1], o[j][3] * inv[1]);
            *(float2*)&orow[16 * DIM + col] = make_float2(o[j][4] * inv[2], o[j][5] * inv[2]);
            *(float2*)&orow[24 * DIM + col] = make_float2(o[j][6] * inv[3], o[j][7] * inv[3]);
        }
    }
}

extern "C" void kernel_launch(void* const* d_in, const int* in_sizes, int n_in,
                              void* d_out, int out_size)
{
    const float* qs = (const float*)d_in[0];
    const float* ks = (const float*)d_in[1];
    const float* vs = (const float*)d_in[2];
    const unsigned int* maskw = (const unsigned int*)d_in[3];
    float* out = (float*)d_out;

    // prepass: round K,V to tf32 into static scratch
    const int total4 = NHEAD * KLEN * DIM / 4;
    kv_round<<<total4 / 256, 256>>>(ks, vs);

    cudaFuncSetAttribute(fa_hmma_ovl, cudaFuncAttributeMaxDynamicSharedMemorySize, SMEM_BYTES);
    dim3 grid(QLEN / BQ, NHEAD);
    fa_hmma_ovl<<<grid, NTHREADS, SMEM_BYTES>>>(qs, maskw, out);
}